// round 15
// baseline (speedup 1.0000x reference)
#include <cuda_runtime.h>
#include <cuda_fp16.h>
#include <math.h>
#include <stdint.h>

// Problem constants
#define S_LEN   2048
#define BATCH   8
#define DIM     512
#define HID     512
#define N3      1536
#define MROWS   16384
#define NODES   7
#define NCHUNK  64
#define CHLEN   32                    // S_LEN / NCHUNK
#define LANES   4096
#define LANES4  1024                  // scan threads handle 4 adjacent h

// fp16 GEMM tiling: 128x128 block tile, BK=64, 8 warps of 64x32, mma m16n8k16
#define BM 128
#define BN 128
#define BK 64
#define NKT (DIM / BK)                // 8 k-tiles
#define APITCH 72
#define BPITCH 136
#define A_ST (BM * APITCH * 2)        // 18432 B
#define B_ST (BK * BPITCH * 2)        // 17408 B
#define STAGE_B (A_ST + B_ST)         // 35840
#define GEMM_SMEM (3 * STAGE_B)       // 107520

#define GPN 1536                      // GEMM blocks per node: 12 * 128
#define TP_GRID 64                    // tproj blocks
#define SCANA_GRID 1024               // 4 nodes * 64 chunks * 4 xb (256 thr)

// conversion grid
#define XH_BLOCKS 4096
#define WH_BLOCKS 2688

// Scratch (static __device__ arrays: allocation-free, graph-safe)
// g_V holds raw GEMM output; scans overwrite it in place with FUSED gates:
//   z <- relu(z), f <- sigmoid(f_merged), o <- sigmoid(o_merged)
__device__ __align__(256) __half g_V [(size_t)NODES * MROWS * N3];
__device__ __align__(256) float  g_T [(size_t)NODES * MROWS * 2];
__device__ __align__(256) float  g_A [(size_t)NODES * NCHUNK * LANES];
__device__ __align__(256) float  g_Bc[(size_t)NODES * NCHUNK * LANES];
__device__ __align__(256) float  g_CM[(size_t)NCHUNK * LANES];
__device__ __align__(256) __half g_Xh[(size_t)MROWS * DIM];
__device__ __align__(256) __half g_Wh[(size_t)NODES * DIM * N3];

__device__ __forceinline__ float sigmoidf(float x) {
    return __fdividef(1.0f, 1.0f + __expf(-x));
}
__device__ __forceinline__ uint32_t smem_u32(const void* p) {
    return (uint32_t)__cvta_generic_to_shared(p);
}
__device__ __forceinline__ void cp_async16(uint32_t dst, const void* src) {
    asm volatile("cp.async.cg.shared.global [%0], [%1], 16;\n" :: "r"(dst), "l"(src));
}
__device__ __forceinline__ void cp_commit() { asm volatile("cp.async.commit_group;\n"); }
template<int N> __device__ __forceinline__ void cp_wait() {
    asm volatile("cp.async.wait_group %0;\n" :: "n"(N));
}
__device__ __forceinline__ void ldsm_x4(uint32_t* r, uint32_t addr) {
    asm volatile("ldmatrix.sync.aligned.m8n8.x4.shared.b16 {%0,%1,%2,%3}, [%4];"
                 : "=r"(r[0]), "=r"(r[1]), "=r"(r[2]), "=r"(r[3]) : "r"(addr));
}
__device__ __forceinline__ void ldsm_x4_t(uint32_t* r, uint32_t addr) {
    asm volatile("ldmatrix.sync.aligned.m8n8.x4.trans.shared.b16 {%0,%1,%2,%3}, [%4];"
                 : "=r"(r[0]), "=r"(r[1]), "=r"(r[2]), "=r"(r[3]) : "r"(addr));
}
__device__ __forceinline__ void mma_f16(float* c, const uint32_t* a,
                                        uint32_t b0, uint32_t b1) {
    asm volatile(
        "mma.sync.aligned.m16n8k16.row.col.f32.f16.f16.f32 "
        "{%0,%1,%2,%3}, {%4,%5,%6,%7}, {%8,%9}, {%0,%1,%2,%3};\n"
        : "+f"(c[0]), "+f"(c[1]), "+f"(c[2]), "+f"(c[3])
        : "r"(a[0]), "r"(a[1]), "r"(a[2]), "r"(a[3]), "r"(b0), "r"(b1));
}

// 4-half vector load/store helpers for the scans
__device__ __forceinline__ void ldh4(const __half* p, float* o) {
    uint2 u = *(const uint2*)p;
    __half2 h0 = *reinterpret_cast<__half2*>(&u.x);
    __half2 h1 = *reinterpret_cast<__half2*>(&u.y);
    float2 a = __half22float2(h0), b = __half22float2(h1);
    o[0] = a.x; o[1] = a.y; o[2] = b.x; o[3] = b.y;
}
__device__ __forceinline__ void sth4(__half* p, const float* o) {
    __half2 h0 = __floats2half2_rn(o[0], o[1]);
    __half2 h1 = __floats2half2_rn(o[2], o[3]);
    uint2 u;
    u.x = *reinterpret_cast<uint32_t*>(&h0);
    u.y = *reinterpret_cast<uint32_t*>(&h1);
    *(uint2*)p = u;
}

// ---------------------------------------------------------------------------
// conv: X->fp16 | W->fp16
// ---------------------------------------------------------------------------
__global__ __launch_bounds__(256) void conv_kernel(const float* __restrict__ X,
                                                   const float* __restrict__ Wp) {
    const int bid = blockIdx.x;
    const int tid = threadIdx.x;
    const float* src;
    __half* dst;
    size_t e0;
    if (bid < XH_BLOCKS) {
        e0 = (size_t)bid * 2048 + tid * 8;
        src = X; dst = g_Xh;
    } else {
        e0 = (size_t)(bid - XH_BLOCKS) * 2048 + tid * 8;
        src = Wp; dst = g_Wh;
    }
    const float4 v0 = *(const float4*)(src + e0);
    const float4 v1 = *(const float4*)(src + e0 + 4);
    __half2 h[4];
    h[0] = __floats2half2_rn(v0.x, v0.y);
    h[1] = __floats2half2_rn(v0.z, v0.w);
    h[2] = __floats2half2_rn(v1.x, v1.y);
    h[3] = __floats2half2_rn(v1.z, v1.w);
    *(uint4*)(dst + e0) = *(uint4*)h;
}

// ---------------------------------------------------------------------------
// GEMM body: V[node] tile (mb, nb) = Xh @ Wh[node], fp16 store.
// ---------------------------------------------------------------------------
__device__ __forceinline__ void gemm_stage_load(uint32_t aB, uint32_t bB,
                                                const __half* __restrict__ Ag,
                                                const __half* __restrict__ Bg,
                                                int k0, int tid) {
    #pragma unroll
    for (int i = 0; i < 4; i++) {
        const int id = i * 256 + tid;
        const int m = id >> 3, c = id & 7;
        cp_async16(aB + (uint32_t)(m * (APITCH * 2) + c * 16),
                   Ag + (size_t)m * DIM + k0 + c * 8);
    }
    #pragma unroll
    for (int i = 0; i < 4; i++) {
        const int id = i * 256 + tid;
        const int k = id >> 4, c = id & 15;
        cp_async16(bB + (uint32_t)(k * (BPITCH * 2) + c * 16),
                   Bg + (size_t)(k0 + k) * N3 + c * 8);
    }
    cp_commit();
}

__device__ void gemm_body(char* dynsmem, int node, int mb, int nb, int tid) {
    const int n0 = nb * BN;
    const int m0 = mb * BM;
    const __half* Ag = g_Xh + (size_t)m0 * DIM;
    const __half* Bg = g_Wh + (size_t)node * DIM * N3 + n0;
    __half* C = g_V + (size_t)node * MROWS * N3;

    const int w = tid >> 5;
    const int lane = tid & 31;
    const int gid = lane >> 2;
    const int tig = lane & 3;
    const int wm = (w >> 2) * 64;
    const int wn = (w & 3) * 32;

    const int rowb = (lane & 7) + ((lane >> 3) & 1) * 8;
    const int choff = lane >> 4;

    const uint32_t sbase = smem_u32(dynsmem);

    float acc[4][4][4];
    #pragma unroll
    for (int mi = 0; mi < 4; mi++)
        #pragma unroll
        for (int ni = 0; ni < 4; ni++)
            #pragma unroll
            for (int c = 0; c < 4; c++) acc[mi][ni][c] = 0.0f;

    gemm_stage_load(sbase, sbase + A_ST, Ag, Bg, 0, tid);
    gemm_stage_load(sbase + STAGE_B, sbase + STAGE_B + A_ST, Ag, Bg, BK, tid);

    int s = 0;
    #pragma unroll 1
    for (int kt = 0; kt < NKT; kt++) {
        if (kt == NKT - 1) cp_wait<0>(); else cp_wait<1>();
        __syncthreads();
        if (kt + 2 < NKT) {
            const int ps = (s + 2 >= 3) ? (s - 1) : (s + 2);
            gemm_stage_load(sbase + (uint32_t)ps * STAGE_B,
                            sbase + (uint32_t)ps * STAGE_B + A_ST,
                            Ag, Bg, (kt + 2) * BK, tid);
        }

        const uint32_t aBase = sbase + (uint32_t)s * STAGE_B;
        const uint32_t bBase = aBase + A_ST;

        #pragma unroll
        for (int j = 0; j < 4; j++) {
            uint32_t a[4][4], b[2][4];
            #pragma unroll
            for (int mi = 0; mi < 4; mi++) {
                const int row = wm + mi * 16 + rowb;
                const int chunk = 2 * j + choff;
                ldsm_x4(a[mi], aBase + (uint32_t)(row * (APITCH * 2) + chunk * 16));
            }
            #pragma unroll
            for (int p = 0; p < 2; p++) {
                const int row = 16 * j + rowb;
                const int chunk = (wn >> 3) + 2 * p + choff;
                ldsm_x4_t(b[p], bBase + (uint32_t)(row * (BPITCH * 2) + chunk * 16));
            }
            #pragma unroll
            for (int mi = 0; mi < 4; mi++)
                #pragma unroll
                for (int ni = 0; ni < 4; ni++)
                    mma_f16(acc[mi][ni], a[mi],
                            b[ni >> 1][(ni & 1) * 2], b[ni >> 1][(ni & 1) * 2 + 1]);
        }
        s = (s + 1 >= 3) ? 0 : (s + 1);
    }

    #pragma unroll
    for (int mi = 0; mi < 4; mi++) {
        #pragma unroll
        for (int ni = 0; ni < 4; ni++) {
            const int row = m0 + wm + mi * 16 + gid;
            const int col = n0 + wn + ni * 8 + tig * 2;
            *(__half2*)&C[(size_t)row * N3 + col] =
                __floats2half2_rn(acc[mi][ni][0], acc[mi][ni][1]);
            *(__half2*)&C[(size_t)(row + 8) * N3 + col] =
                __floats2half2_rn(acc[mi][ni][2], acc[mi][ni][3]);
        }
    }
}

// ---------------------------------------------------------------------------
// tproj body: all 7 nodes' gates, W_T table in dynamic smem
// ---------------------------------------------------------------------------
__device__ void tproj_body(char* dynsmem, int blk,
                           const float* __restrict__ X,
                           const float* __restrict__ WT,
                           const float* __restrict__ bT, int tid) {
    float (*swt)[NODES][DIM] = (float (*)[NODES][DIM])dynsmem;
    for (int idx = tid; idx < NODES * DIM * 2; idx += 256) {
        const int node = idx / (DIM * 2);
        const int r = idx - node * DIM * 2;
        swt[r & 1][node][r >> 1] = WT[idx];
    }
    __syncthreads();

    const int w = tid >> 5;
    const int lane = tid & 31;
    const int m0 = blk * 256 + w * 32;

    float bt[NODES][2];
    #pragma unroll
    for (int n = 0; n < NODES; n++) {
        bt[n][0] = bT[n * 2 + 0];
        bt[n][1] = bT[n * 2 + 1];
    }
    for (int r = 0; r < 32; r++) {
        const int m = m0 + r;
        const float* xr = X + (size_t)m * DIM;
        float s[NODES][2];
        #pragma unroll
        for (int n = 0; n < NODES; n++) s[n][0] = s[n][1] = 0.0f;
        #pragma unroll 4
        for (int k = lane; k < DIM; k += 32) {
            const float x = xr[k];
            #pragma unroll
            for (int n = 0; n < NODES; n++) {
                s[n][0] = fmaf(x, swt[0][n][k], s[n][0]);
                s[n][1] = fmaf(x, swt[1][n][k], s[n][1]);
            }
        }
        #pragma unroll
        for (int n = 0; n < NODES; n++)
            #pragma unroll
            for (int j = 0; j < 2; j++)
                #pragma unroll
                for (int o = 16; o > 0; o >>= 1)
                    s[n][j] += __shfl_down_sync(0xFFFFFFFFu, s[n][j], o);
        if (lane == 0) {
            #pragma unroll
            for (int n = 0; n < NODES; n++) {
                const size_t t = ((size_t)n * MROWS + m) * 2;
                g_T[t + 0] = sigmoidf(s[n][0] + bt[n][0]);
                g_T[t + 1] = sigmoidf(s[n][1] + bt[n][1]);
            }
        }
    }
}

// ---------------------------------------------------------------------------
// scanA leaf body: fuse gates in place (relu z / sig f / sig o) + summary.
// ---------------------------------------------------------------------------
__device__ void scanA_body(int node, int chunk, int l4) {
    const int b  = l4 >> 7;
    const int h0 = (l4 & 127) * 4;
    __half* Vn = g_V + (size_t)node * MROWS * N3;

    float A[4], Bs[4];
    #pragma unroll
    for (int q = 0; q < 4; q++) { A[q] = 1.0f; Bs[q] = 0.0f; }

    const int s0 = chunk * CHLEN;
    #pragma unroll 4
    for (int si = 0; si < CHLEN; si++) {
        const int m = (s0 + si) * BATCH + b;
        const size_t vi = (size_t)m * N3 + h0;
        float z[4], f[4], o[4];
        ldh4(Vn + vi, z);
        ldh4(Vn + vi + HID, f);
        ldh4(Vn + vi + 2 * HID, o);
        #pragma unroll
        for (int q = 0; q < 4; q++) {
            z[q] = fmaxf(z[q], 0.0f);
            f[q] = sigmoidf(f[q]);
            o[q] = sigmoidf(o[q]);
            const float a = 1.0f - f[q];
            A[q] *= a;
            Bs[q] = fmaf(a, Bs[q], f[q] * z[q]);
        }
        sth4(Vn + vi, z);
        sth4(Vn + vi + HID, f);
        sth4(Vn + vi + 2 * HID, o);
    }
    const size_t idx = ((size_t)node * NCHUNK + chunk) * LANES + b * 512 + h0;
    *(float4*)&g_A[idx]  = make_float4(A[0], A[1], A[2], A[3]);
    *(float4*)&g_Bc[idx] = make_float4(Bs[0], Bs[1], Bs[2], Bs[3]);
}

// ---------------------------------------------------------------------------
// K1: leaf GEMMs (nodes 3..6) + tproj
// ---------------------------------------------------------------------------
__global__ __launch_bounds__(256, 2) void k1_kernel(const float* __restrict__ X,
                                                    const float* __restrict__ WT,
                                                    const float* __restrict__ bT) {
    extern __shared__ __align__(16) char dynsmem[];
    const int bid = blockIdx.x;
    const int tid = threadIdx.x;
    if (bid < 4 * GPN) {
        const int node = 3 + bid / GPN;
        const int r = bid % GPN;
        gemm_body(dynsmem, node, r / 12, r % 12, tid);
    } else {
        tproj_body(dynsmem, bid - 4 * GPN, X, WT, bT, tid);
    }
}

// ---------------------------------------------------------------------------
// K2: internal GEMMs (nodes 0..2) + leaf scanA/fuse
// ---------------------------------------------------------------------------
__global__ __launch_bounds__(256, 2) void k2_kernel() {
    extern __shared__ __align__(16) char dynsmem[];
    const int bid = blockIdx.x;
    const int tid = threadIdx.x;
    if (bid < 3 * GPN) {
        const int node = bid / GPN;
        const int r = bid % GPN;
        gemm_body(dynsmem, node, r / 12, r % 12, tid);
    } else {
        const int sid = bid - 3 * GPN;            // 0..1023
        const int node = 3 + (sid >> 8);          // 256 blocks per node
        const int rem = sid & 255;
        const int chunk = rem >> 2;               // 64 chunks
        const int xb = rem & 3;
        scanA_body(node, chunk, xb * 256 + tid);
    }
}

// ---------------------------------------------------------------------------
// Level kernel: children scanB (FUSED gates, pure FMA) + parent fuse + scanA.
// Children Hout stays in-register; parent's fused gates overwrite g_V[p].
// ---------------------------------------------------------------------------
__global__ __launch_bounds__(128) void klevel_kernel(int p0, const float* __restrict__ X) {
    const int p  = p0 + blockIdx.z;
    const int c1 = 2 * p + 1;
    const int c2 = 2 * p + 2;
    const int chunk = blockIdx.y;
    const int l4 = blockIdx.x * 128 + threadIdx.x;
    const int b  = l4 >> 7;
    const int h0 = (l4 & 127) * 4;
    const int L = b * 512 + h0;

    const __half* V1 = g_V + (size_t)c1 * MROWS * N3;   // fused
    const __half* V2 = g_V + (size_t)c2 * MROWS * N3;   // fused
    __half* Vp = g_V + (size_t)p * MROWS * N3;          // raw -> fused
    const float* Tp = g_T + (size_t)p * MROWS * 2;

    float p1[4], p2[4];
    #pragma unroll
    for (int q = 0; q < 4; q++) { p1[q] = 0.0f; p2[q] = 0.0f; }
    {
        const float* A1p = g_A  + (size_t)c1 * NCHUNK * LANES + L;
        const float* B1p = g_Bc + (size_t)c1 * NCHUNK * LANES + L;
        const float* A2p = g_A  + (size_t)c2 * NCHUNK * LANES + L;
        const float* B2p = g_Bc + (size_t)c2 * NCHUNK * LANES + L;
        #pragma unroll 2
        for (int j = 0; j < chunk; j++) {
            const float4 a1 = *(const float4*)(A1p + (size_t)j * LANES);
            const float4 b1 = *(const float4*)(B1p + (size_t)j * LANES);
            const float4 a2 = *(const float4*)(A2p + (size_t)j * LANES);
            const float4 b2 = *(const float4*)(B2p + (size_t)j * LANES);
            p1[0] = fmaf(a1.x, p1[0], b1.x);
            p1[1] = fmaf(a1.y, p1[1], b1.y);
            p1[2] = fmaf(a1.z, p1[2], b1.z);
            p1[3] = fmaf(a1.w, p1[3], b1.w);
            p2[0] = fmaf(a2.x, p2[0], b2.x);
            p2[1] = fmaf(a2.y, p2[1], b2.y);
            p2[2] = fmaf(a2.z, p2[2], b2.z);
            p2[3] = fmaf(a2.w, p2[3], b2.w);
        }
    }

    float PA[4], PB[4];
    #pragma unroll
    for (int q = 0; q < 4; q++) { PA[q] = 1.0f; PB[q] = 0.0f; }

    const int s0 = chunk * CHLEN;
    #pragma unroll 2
    for (int si = 0; si < CHLEN; si++) {
        const int m = (s0 + si) * BATCH + b;
        const float4 xr = *(const float4*)(X + (size_t)m * DIM + h0);
        const float xv[4] = { xr.x, xr.y, xr.z, xr.w };
        const size_t vi = (size_t)m * N3 + h0;

        // child 1 scanB (fused gates: pure FMA)
        float h1[4];
        {
            float zr[4], fs[4], os[4];
            ldh4(V1 + vi, zr);
            ldh4(V1 + vi + HID, fs);
            ldh4(V1 + vi + 2 * HID, os);
            #pragma unroll
            for (int q = 0; q < 4; q++) {
                p1[q] = fmaf(fs[q], zr[q], (1.0f - fs[q]) * p1[q]);
                h1[q] = p1[q] * os[q] + xv[q];
            }
        }
        // child 2 scanB
        float h2[4];
        {
            float zr[4], fs[4], os[4];
            ldh4(V2 + vi, zr);
            ldh4(V2 + vi + HID, fs);
            ldh4(V2 + vi + 2 * HID, os);
            #pragma unroll
            for (int q = 0; q < 4; q++) {
                p2[q] = fmaf(fs[q], zr[q], (1.0f - fs[q]) * p2[q]);
                h2[q] = p2[q] * os[q] + xv[q];
            }
        }
        // parent: merge + activate + store fused + scanA summary
        {
            const float2 t = *(const float2*)(Tp + (size_t)m * 2);
            float z[4], f[4], o[4];
            ldh4(Vp + vi, z);
            ldh4(Vp + vi + HID, f);
            ldh4(Vp + vi + 2 * HID, o);
            #pragma unroll
            for (int q = 0; q < 4; q++) {
                const float fm = h1[q] * t.x + (1.0f - t.x) * f[q];
                const float om = h2[q] * t.y + (1.0f - t.y) * o[q];
                z[q] = fmaxf(z[q], 0.0f);
                f[q] = sigmoidf(fm);
                o[q] = sigmoidf(om);
                const float a = 1.0f - f[q];
                PA[q] *= a;
                PB[q] = fmaf(a, PB[q], f[q] * z[q]);
            }
            sth4(Vp + vi, z);
            sth4(Vp + vi + HID, f);
            sth4(Vp + vi + 2 * HID, o);
        }
    }
    const size_t idx = ((size_t)p * NCHUNK + chunk) * LANES + L;
    *(float4*)&g_A[idx]  = make_float4(PA[0], PA[1], PA[2], PA[3]);
    *(float4*)&g_Bc[idx] = make_float4(PB[0], PB[1], PB[2], PB[3]);
}

// ---------------------------------------------------------------------------
// Root scanB: fused gates of node 0, pure streaming FMA.
// ---------------------------------------------------------------------------
__global__ __launch_bounds__(128) void kroot_kernel(const float* __restrict__ X,
                                                    float* __restrict__ out) {
    const int chunk = blockIdx.y;
    const int l4 = blockIdx.x * 128 + threadIdx.x;
    const int b  = l4 >> 7;
    const int h0 = (l4 & 127) * 4;
    const int L = b * 512 + h0;
    const __half* Vn = g_V;   // fused root gates

    float c[4];
    #pragma unroll
    for (int q = 0; q < 4; q++) c[q] = 0.0f;
    {
        const float* Ap = g_A  + L;
        const float* Bp = g_Bc + L;
        #pragma unroll 2
        for (int j = 0; j < chunk; j++) {
            const float4 a  = *(const float4*)(Ap + (size_t)j * LANES);
            const float4 bb = *(const float4*)(Bp + (size_t)j * LANES);
            c[0] = fmaf(a.x, c[0], bb.x);
            c[1] = fmaf(a.y, c[1], bb.y);
            c[2] = fmaf(a.z, c[2], bb.z);
            c[3] = fmaf(a.w, c[3], bb.w);
        }
    }

    float cm[4];
    #pragma unroll
    for (int q = 0; q < 4; q++) cm[q] = -3.4e38f;

    const int s0 = chunk * CHLEN;
    #pragma unroll 4
    for (int si = 0; si < CHLEN; si++) {
        const int m = (s0 + si) * BATCH + b;
        const size_t vi = (size_t)m * N3 + h0;
        float zr[4], fs[4], os[4];
        ldh4(Vn + vi, zr);
        ldh4(Vn + vi + HID, fs);
        ldh4(Vn + vi + 2 * HID, os);
        const float4 xr = *(const float4*)(X + (size_t)m * DIM + h0);
        const float xv[4] = { xr.x, xr.y, xr.z, xr.w };
        float ov[4];
        #pragma unroll
        for (int q = 0; q < 4; q++) {
            c[q] = fmaf(fs[q], zr[q], (1.0f - fs[q]) * c[q]);
            const float v = c[q] * os[q];
            cm[q] = fmaxf(cm[q], v);
            ov[q] = v + xv[q];
        }
        *(float4*)&out[(size_t)m * HID + h0] = make_float4(ov[0], ov[1], ov[2], ov[3]);
    }
    *(float4*)&g_CM[(size_t)chunk * LANES + L] = make_float4(cm[0], cm[1], cm[2], cm[3]);
}

__global__ __launch_bounds__(128) void cmax_kernel(float* __restrict__ cmax_out) {
    const int lane = blockIdx.x * 128 + threadIdx.x;
    float cm = -3.4e38f;
    #pragma unroll 4
    for (int j = 0; j < NCHUNK; j++)
        cm = fmaxf(cm, g_CM[(size_t)j * LANES + lane]);
    cmax_out[lane] = cm;
}

// ---------------------------------------------------------------------------
extern "C" void kernel_launch(void* const* d_in, const int* in_sizes, int n_in,
                              void* d_out, int out_size) {
    const float* X  = (const float*)d_in[0];
    const float* Wp = (const float*)d_in[1];
    const float* WT = (const float*)d_in[2];
    const float* bT = (const float*)d_in[3];
    float* out = (float*)d_out;
    (void)in_sizes; (void)n_in;

    cudaFuncSetAttribute(k1_kernel,
                         cudaFuncAttributeMaxDynamicSharedMemorySize, GEMM_SMEM);
    cudaFuncSetAttribute(k2_kernel,
                         cudaFuncAttributeMaxDynamicSharedMemorySize, GEMM_SMEM);

    // 1: fp16 conversions
    conv_kernel<<<XH_BLOCKS + WH_BLOCKS, 256>>>(X, Wp);
    // 2: leaf GEMMs + tproj
    k1_kernel<<<4 * GPN + TP_GRID, 256, GEMM_SMEM>>>(X, WT, bT);
    // 3: internal GEMMs + leaf scanA/fuse (GEMM-shadowed)
    k2_kernel<<<3 * GPN + SCANA_GRID, 256, GEMM_SMEM>>>();
    // 4: children 3..6 scanB + parents 1,2 fuse/scanA   <-- ncu slot
    klevel_kernel<<<dim3(LANES4 / 128, NCHUNK, 2), 128>>>(1, X);
    // 5: children 1,2 scanB + root fuse/scanA
    klevel_kernel<<<dim3(LANES4 / 128, NCHUNK, 1), 128>>>(0, X);
    // 6: root scanB + per-chunk cmax
    kroot_kernel<<<dim3(LANES4 / 128, NCHUNK), 128>>>(X, out);
    // 7: cmax second output
    if (out_size >= MROWS * HID + LANES)
        cmax_kernel<<<LANES / 128, 128>>>(out + (size_t)MROWS * HID);
}

// round 16
// speedup vs baseline: 1.0241x; 1.0241x over previous
#include <cuda_runtime.h>
#include <cuda_fp16.h>
#include <math.h>
#include <stdint.h>

// Problem constants
#define S_LEN   2048
#define BATCH   8
#define DIM     512
#define HID     512
#define N3      1536
#define MROWS   16384
#define NODES   7
#define NCHUNK  64
#define CHLEN   32                    // S_LEN / NCHUNK
#define LANES   4096
#define LANES4  1024                  // scan threads handle 4 adjacent h

// fp16 GEMM tiling: 128x256 block tile, BK=64, 8 warps of 64x64, mma m16n8k16
#define BM 128
#define BN 256
#define BK 64
#define NKT (DIM / BK)                // 8 k-tiles
#define APITCH 72                     // halves per A smem row (64 data + 8 pad)
#define BPITCH 264                    // halves per B smem row (256 data + 8 pad)
#define A_ST (BM * APITCH * 2)        // 18432 B
#define B_ST (BK * BPITCH * 2)        // 33792 B
#define STAGE_B (A_ST + B_ST)        // 52224
#define GEMM_SMEM (3 * STAGE_B)      // 156672

#define GPN 768                       // GEMM blocks per node: 6 * 128
#define TP_GRID 64                    // tproj blocks
#define SCANA_GRID 1024               // 4 nodes * 64 chunks * 4 xb (256 thr)

// conversion grid
#define XH_BLOCKS 4096
#define WH_BLOCKS 2688

// Scratch (static __device__ arrays: allocation-free, graph-safe)
__device__ __align__(256) __half g_V [(size_t)NODES * MROWS * N3];
__device__ __align__(256) __half g_Hh[(size_t)6 * MROWS * HID];
__device__ __align__(256) float  g_T [(size_t)NODES * MROWS * 2];
__device__ __align__(256) float  g_A [(size_t)NODES * NCHUNK * LANES];
__device__ __align__(256) float  g_Bc[(size_t)NODES * NCHUNK * LANES];
__device__ __align__(256) float  g_CM[(size_t)NCHUNK * LANES];
__device__ __align__(256) __half g_Xh[(size_t)MROWS * DIM];
__device__ __align__(256) __half g_Wh[(size_t)NODES * DIM * N3];

__device__ __forceinline__ float sigmoidf(float x) {
    return __fdividef(1.0f, 1.0f + __expf(-x));
}
__device__ __forceinline__ uint32_t smem_u32(const void* p) {
    return (uint32_t)__cvta_generic_to_shared(p);
}
__device__ __forceinline__ void cp_async16(uint32_t dst, const void* src) {
    asm volatile("cp.async.cg.shared.global [%0], [%1], 16;\n" :: "r"(dst), "l"(src));
}
__device__ __forceinline__ void cp_commit() { asm volatile("cp.async.commit_group;\n"); }
template<int N> __device__ __forceinline__ void cp_wait() {
    asm volatile("cp.async.wait_group %0;\n" :: "n"(N));
}
__device__ __forceinline__ void ldsm_x4(uint32_t* r, uint32_t addr) {
    asm volatile("ldmatrix.sync.aligned.m8n8.x4.shared.b16 {%0,%1,%2,%3}, [%4];"
                 : "=r"(r[0]), "=r"(r[1]), "=r"(r[2]), "=r"(r[3]) : "r"(addr));
}
__device__ __forceinline__ void ldsm_x4_t(uint32_t* r, uint32_t addr) {
    asm volatile("ldmatrix.sync.aligned.m8n8.x4.trans.shared.b16 {%0,%1,%2,%3}, [%4];"
                 : "=r"(r[0]), "=r"(r[1]), "=r"(r[2]), "=r"(r[3]) : "r"(addr));
}
__device__ __forceinline__ void mma_f16(float* c, const uint32_t* a,
                                        uint32_t b0, uint32_t b1) {
    asm volatile(
        "mma.sync.aligned.m16n8k16.row.col.f32.f16.f16.f32 "
        "{%0,%1,%2,%3}, {%4,%5,%6,%7}, {%8,%9}, {%0,%1,%2,%3};\n"
        : "+f"(c[0]), "+f"(c[1]), "+f"(c[2]), "+f"(c[3])
        : "r"(a[0]), "r"(a[1]), "r"(a[2]), "r"(a[3]), "r"(b0), "r"(b1));
}

// 4-half vector load/store helpers for the scans
__device__ __forceinline__ void ldh4(const __half* p, float* o) {
    uint2 u = *(const uint2*)p;
    __half2 h0 = *reinterpret_cast<__half2*>(&u.x);
    __half2 h1 = *reinterpret_cast<__half2*>(&u.y);
    float2 a = __half22float2(h0), b = __half22float2(h1);
    o[0] = a.x; o[1] = a.y; o[2] = b.x; o[3] = b.y;
}
__device__ __forceinline__ void sth4(__half* p, const float* o) {
    __half2 h0 = __floats2half2_rn(o[0], o[1]);
    __half2 h1 = __floats2half2_rn(o[2], o[3]);
    uint2 u;
    u.x = *reinterpret_cast<uint32_t*>(&h0);
    u.y = *reinterpret_cast<uint32_t*>(&h1);
    *(uint2*)p = u;
}

// ---------------------------------------------------------------------------
// conv: X->fp16 | W->fp16
// ---------------------------------------------------------------------------
__global__ __launch_bounds__(256) void conv_kernel(const float* __restrict__ X,
                                                   const float* __restrict__ Wp) {
    const int bid = blockIdx.x;
    const int tid = threadIdx.x;
    const float* src;
    __half* dst;
    size_t e0;
    if (bid < XH_BLOCKS) {
        e0 = (size_t)bid * 2048 + tid * 8;
        src = X; dst = g_Xh;
    } else {
        e0 = (size_t)(bid - XH_BLOCKS) * 2048 + tid * 8;
        src = Wp; dst = g_Wh;
    }
    const float4 v0 = *(const float4*)(src + e0);
    const float4 v1 = *(const float4*)(src + e0 + 4);
    __half2 h[4];
    h[0] = __floats2half2_rn(v0.x, v0.y);
    h[1] = __floats2half2_rn(v0.z, v0.w);
    h[2] = __floats2half2_rn(v1.x, v1.y);
    h[3] = __floats2half2_rn(v1.z, v1.w);
    *(uint4*)(dst + e0) = *(uint4*)h;
}

// ---------------------------------------------------------------------------
// GEMM body: V[node] tile (mb, nb) = Xh @ Wh[node], fp16 store.
// 256 threads / 8 warps (64x64), 128x256 block tile, BK=64, 3-stage cp.async.
// ---------------------------------------------------------------------------
__device__ __forceinline__ void gemm_stage_load(uint32_t aB, uint32_t bB,
                                                const __half* __restrict__ Ag,
                                                const __half* __restrict__ Bg,
                                                int k0, int tid) {
    // A: 128 rows x 8 chunks of 8 halves = 1024 chunks
    #pragma unroll
    for (int i = 0; i < 4; i++) {
        const int id = i * 256 + tid;
        const int m = id >> 3, c = id & 7;
        cp_async16(aB + (uint32_t)(m * (APITCH * 2) + c * 16),
                   Ag + (size_t)m * DIM + k0 + c * 8);
    }
    // B: 64 rows x 32 chunks of 8 halves = 2048 chunks
    #pragma unroll
    for (int i = 0; i < 8; i++) {
        const int id = i * 256 + tid;
        const int k = id >> 5, c = id & 31;
        cp_async16(bB + (uint32_t)(k * (BPITCH * 2) + c * 16),
                   Bg + (size_t)(k0 + k) * N3 + c * 8);
    }
    cp_commit();
}

__device__ void gemm_body(char* dynsmem, int node, int mb, int nb, int tid) {
    const int n0 = nb * BN;
    const int m0 = mb * BM;
    const __half* Ag = g_Xh + (size_t)m0 * DIM;
    const __half* Bg = g_Wh + (size_t)node * DIM * N3 + n0;
    __half* C = g_V + (size_t)node * MROWS * N3;

    const int w = tid >> 5;
    const int lane = tid & 31;
    const int gid = lane >> 2;
    const int tig = lane & 3;
    const int wm = (w >> 2) * 64;     // 2 warp rows
    const int wn = (w & 3) * 64;      // 4 warp cols, 64 wide

    const int rowb = (lane & 7) + ((lane >> 3) & 1) * 8;
    const int choff = lane >> 4;

    const uint32_t sbase = smem_u32(dynsmem);

    float acc[4][8][4];
    #pragma unroll
    for (int mi = 0; mi < 4; mi++)
        #pragma unroll
        for (int ni = 0; ni < 8; ni++)
            #pragma unroll
            for (int c = 0; c < 4; c++) acc[mi][ni][c] = 0.0f;

    gemm_stage_load(sbase, sbase + A_ST, Ag, Bg, 0, tid);
    gemm_stage_load(sbase + STAGE_B, sbase + STAGE_B + A_ST, Ag, Bg, BK, tid);

    int s = 0;
    #pragma unroll 1
    for (int kt = 0; kt < NKT; kt++) {
        if (kt == NKT - 1) cp_wait<0>(); else cp_wait<1>();
        __syncthreads();
        if (kt + 2 < NKT) {
            const int ps = (s + 2 >= 3) ? (s - 1) : (s + 2);
            gemm_stage_load(sbase + (uint32_t)ps * STAGE_B,
                            sbase + (uint32_t)ps * STAGE_B + A_ST,
                            Ag, Bg, (kt + 2) * BK, tid);
        }

        const uint32_t aBase = sbase + (uint32_t)s * STAGE_B;
        const uint32_t bBase = aBase + A_ST;

        #pragma unroll
        for (int j = 0; j < 4; j++) {          // 4 x k16 per ktile
            uint32_t a[4][4], b[4][4];
            #pragma unroll
            for (int mi = 0; mi < 4; mi++) {
                const int row = wm + mi * 16 + rowb;
                const int chunk = 2 * j + choff;
                ldsm_x4(a[mi], aBase + (uint32_t)(row * (APITCH * 2) + chunk * 16));
            }
            #pragma unroll
            for (int p = 0; p < 4; p++) {      // 4 x 16n covers 64 n
                const int row = 16 * j + rowb;
                const int chunk = (wn >> 3) + 2 * p + choff;
                ldsm_x4_t(b[p], bBase + (uint32_t)(row * (BPITCH * 2) + chunk * 16));
            }
            #pragma unroll
            for (int mi = 0; mi < 4; mi++)
                #pragma unroll
                for (int ni = 0; ni < 8; ni++)
                    mma_f16(acc[mi][ni], a[mi],
                            b[ni >> 1][(ni & 1) * 2], b[ni >> 1][(ni & 1) * 2 + 1]);
        }
        s = (s + 1 >= 3) ? 0 : (s + 1);
    }

    #pragma unroll
    for (int mi = 0; mi < 4; mi++) {
        #pragma unroll
        for (int ni = 0; ni < 8; ni++) {
            const int row = m0 + wm + mi * 16 + gid;
            const int col = n0 + wn + ni * 8 + tig * 2;
            *(__half2*)&C[(size_t)row * N3 + col] =
                __floats2half2_rn(acc[mi][ni][0], acc[mi][ni][1]);
            *(__half2*)&C[(size_t)(row + 8) * N3 + col] =
                __floats2half2_rn(acc[mi][ni][2], acc[mi][ni][3]);
        }
    }
}

// ---------------------------------------------------------------------------
// tproj body: all 7 nodes' gates, W_T table in dynamic smem
// ---------------------------------------------------------------------------
__device__ void tproj_body(char* dynsmem, int blk,
                           const float* __restrict__ X,
                           const float* __restrict__ WT,
                           const float* __restrict__ bT, int tid) {
    float (*swt)[NODES][DIM] = (float (*)[NODES][DIM])dynsmem;
    for (int idx = tid; idx < NODES * DIM * 2; idx += 256) {
        const int node = idx / (DIM * 2);
        const int r = idx - node * DIM * 2;
        swt[r & 1][node][r >> 1] = WT[idx];
    }
    __syncthreads();

    const int w = tid >> 5;
    const int lane = tid & 31;
    const int m0 = blk * 256 + w * 32;

    float bt[NODES][2];
    #pragma unroll
    for (int n = 0; n < NODES; n++) {
        bt[n][0] = bT[n * 2 + 0];
        bt[n][1] = bT[n * 2 + 1];
    }
    for (int r = 0; r < 32; r++) {
        const int m = m0 + r;
        const float* xr = X + (size_t)m * DIM;
        float s[NODES][2];
        #pragma unroll
        for (int n = 0; n < NODES; n++) s[n][0] = s[n][1] = 0.0f;
        #pragma unroll 4
        for (int k = lane; k < DIM; k += 32) {
            const float x = xr[k];
            #pragma unroll
            for (int n = 0; n < NODES; n++) {
                s[n][0] = fmaf(x, swt[0][n][k], s[n][0]);
                s[n][1] = fmaf(x, swt[1][n][k], s[n][1]);
            }
        }
        #pragma unroll
        for (int n = 0; n < NODES; n++)
            #pragma unroll
            for (int j = 0; j < 2; j++)
                #pragma unroll
                for (int o = 16; o > 0; o >>= 1)
                    s[n][j] += __shfl_down_sync(0xFFFFFFFFu, s[n][j], o);
        if (lane == 0) {
            #pragma unroll
            for (int n = 0; n < NODES; n++) {
                const size_t t = ((size_t)n * MROWS + m) * 2;
                g_T[t + 0] = sigmoidf(s[n][0] + bt[n][0]);
                g_T[t + 1] = sigmoidf(s[n][1] + bt[n][1]);
            }
        }
    }
}

// ---------------------------------------------------------------------------
// scanA leaf body (4 h per thread)
// ---------------------------------------------------------------------------
__device__ void scanA_body(int node, int chunk, int l4) {
    const int b  = l4 >> 7;
    const int h0 = (l4 & 127) * 4;
    const __half* Vn = g_V + (size_t)node * MROWS * N3;

    float A[4], Bs[4];
    #pragma unroll
    for (int q = 0; q < 4; q++) { A[q] = 1.0f; Bs[q] = 0.0f; }

    const int s0 = chunk * CHLEN;
    #pragma unroll 4
    for (int si = 0; si < CHLEN; si++) {
        const int m = (s0 + si) * BATCH + b;
        const size_t vi = (size_t)m * N3 + h0;
        float z[4], f[4];
        ldh4(Vn + vi, z);
        ldh4(Vn + vi + HID, f);
        #pragma unroll
        for (int q = 0; q < 4; q++) {
            z[q] = fmaxf(z[q], 0.0f);
            f[q] = sigmoidf(f[q]);
            const float a = 1.0f - f[q];
            A[q] *= a;
            Bs[q] = fmaf(a, Bs[q], f[q] * z[q]);
        }
    }
    const size_t idx = ((size_t)node * NCHUNK + chunk) * LANES + b * 512 + h0;
    *(float4*)&g_A[idx]  = make_float4(A[0], A[1], A[2], A[3]);
    *(float4*)&g_Bc[idx] = make_float4(Bs[0], Bs[1], Bs[2], Bs[3]);
}

// ---------------------------------------------------------------------------
// K1: leaf GEMMs (nodes 3..6) + tproj  (block-range fusion)
// ---------------------------------------------------------------------------
__global__ __launch_bounds__(256, 1) void k1_kernel(const float* __restrict__ X,
                                                    const float* __restrict__ WT,
                                                    const float* __restrict__ bT) {
    extern __shared__ __align__(16) char dynsmem[];
    const int bid = blockIdx.x;
    const int tid = threadIdx.x;
    if (bid < 4 * GPN) {
        const int node = 3 + bid / GPN;
        const int r = bid % GPN;
        gemm_body(dynsmem, node, r / 6, r % 6, tid);
    } else {
        tproj_body(dynsmem, bid - 4 * GPN, X, WT, bT, tid);
    }
}

// ---------------------------------------------------------------------------
// K2: internal GEMMs (nodes 0..2) + scanA for leaves
// ---------------------------------------------------------------------------
__global__ __launch_bounds__(256, 1) void k2_kernel() {
    extern __shared__ __align__(16) char dynsmem[];
    const int bid = blockIdx.x;
    const int tid = threadIdx.x;
    if (bid < 3 * GPN) {
        const int node = bid / GPN;
        const int r = bid % GPN;
        gemm_body(dynsmem, node, r / 6, r % 6, tid);
    } else {
        const int sid = bid - 3 * GPN;            // 0..1023
        const int node = 3 + (sid >> 8);          // 256 blocks per node
        const int rem = sid & 255;
        const int chunk = rem >> 2;               // 64 chunks
        const int xb = rem & 3;
        scanA_body(node, chunk, xb * 256 + tid);
    }
}

// ---------------------------------------------------------------------------
// Level kernel: scanB(children) fused with scanA(parent), 4 h per thread.
// ---------------------------------------------------------------------------
template<bool CI>
__global__ __launch_bounds__(128) void klevel_kernel(int p0, const float* __restrict__ X) {
    const int p  = p0 + blockIdx.z;
    const int c1 = 2 * p + 1;
    const int c2 = 2 * p + 2;
    const int chunk = blockIdx.y;
    const int l4 = blockIdx.x * 128 + threadIdx.x;
    const int b  = l4 >> 7;
    const int h0 = (l4 & 127) * 4;
    const int L = b * 512 + h0;

    const __half* V1 = g_V + (size_t)c1 * MROWS * N3;
    const __half* V2 = g_V + (size_t)c2 * MROWS * N3;
    const __half* Vp = g_V + (size_t)p  * MROWS * N3;
    const float* T1 = g_T + (size_t)c1 * MROWS * 2;
    const float* T2 = g_T + (size_t)c2 * MROWS * 2;
    const float* Tp = g_T + (size_t)p  * MROWS * 2;
    const __half* G1F = g_Hh + (size_t)(2 * c1) * MROWS * HID;
    const __half* G1O = g_Hh + (size_t)(2 * c1 + 1) * MROWS * HID;
    const __half* G2F = g_Hh + (size_t)(2 * c2) * MROWS * HID;
    const __half* G2O = g_Hh + (size_t)(2 * c2 + 1) * MROWS * HID;
    __half* Ho1 = g_Hh + (size_t)(c1 - 1) * MROWS * HID;
    __half* Ho2 = g_Hh + (size_t)(c2 - 1) * MROWS * HID;

    float p1[4], p2[4];
    #pragma unroll
    for (int q = 0; q < 4; q++) { p1[q] = 0.0f; p2[q] = 0.0f; }
    {
        const float* A1p = g_A  + (size_t)c1 * NCHUNK * LANES + L;
        const float* B1p = g_Bc + (size_t)c1 * NCHUNK * LANES + L;
        const float* A2p = g_A  + (size_t)c2 * NCHUNK * LANES + L;
        const float* B2p = g_Bc + (size_t)c2 * NCHUNK * LANES + L;
        #pragma unroll 2
        for (int j = 0; j < chunk; j++) {
            const float4 a1 = *(const float4*)(A1p + (size_t)j * LANES);
            const float4 b1 = *(const float4*)(B1p + (size_t)j * LANES);
            const float4 a2 = *(const float4*)(A2p + (size_t)j * LANES);
            const float4 b2 = *(const float4*)(B2p + (size_t)j * LANES);
            p1[0] = fmaf(a1.x, p1[0], b1.x);
            p1[1] = fmaf(a1.y, p1[1], b1.y);
            p1[2] = fmaf(a1.z, p1[2], b1.z);
            p1[3] = fmaf(a1.w, p1[3], b1.w);
            p2[0] = fmaf(a2.x, p2[0], b2.x);
            p2[1] = fmaf(a2.y, p2[1], b2.y);
            p2[2] = fmaf(a2.z, p2[2], b2.z);
            p2[3] = fmaf(a2.w, p2[3], b2.w);
        }
    }

    float PA[4], PB[4];
    #pragma unroll
    for (int q = 0; q < 4; q++) { PA[q] = 1.0f; PB[q] = 0.0f; }

    const int s0 = chunk * CHLEN;
    #pragma unroll 2
    for (int si = 0; si < CHLEN; si++) {
        const int m = (s0 + si) * BATCH + b;
        const float4 xr = *(const float4*)(X + (size_t)m * DIM + h0);
        const float xv[4] = { xr.x, xr.y, xr.z, xr.w };
        const size_t vi = (size_t)m * N3 + h0;

        // child 1 (F-child) scanB + parent scanA
        {
            float z[4], f[4], o[4];
            ldh4(V1 + vi, z);
            ldh4(V1 + vi + HID, f);
            ldh4(V1 + vi + 2 * HID, o);
            if (CI) {
                const float2 t = *(const float2*)(T1 + (size_t)m * 2);
                float hf[4], ho[4];
                ldh4(G1F + (size_t)m * HID + h0, hf);
                ldh4(G1O + (size_t)m * HID + h0, ho);
                #pragma unroll
                for (int q = 0; q < 4; q++) {
                    f[q] = hf[q] * t.x + (1.0f - t.x) * f[q];
                    o[q] = ho[q] * t.y + (1.0f - t.y) * o[q];
                }
            }
            float h1[4];
            #pragma unroll
            for (int q = 0; q < 4; q++) {
                z[q] = fmaxf(z[q], 0.0f);
                f[q] = sigmoidf(f[q]);
                p1[q] = fmaf(f[q], z[q], (1.0f - f[q]) * p1[q]);
                h1[q] = p1[q] * sigmoidf(o[q]) + xv[q];
            }
            sth4(Ho1 + (size_t)m * HID + h0, h1);

            const float tp = __ldg(Tp + (size_t)m * 2);
            float zp[4], fp[4];
            ldh4(Vp + vi, zp);
            ldh4(Vp + vi + HID, fp);
            #pragma unroll
            for (int q = 0; q < 4; q++) {
                fp[q] = h1[q] * tp + (1.0f - tp) * fp[q];
                zp[q] = fmaxf(zp[q], 0.0f);
                fp[q] = sigmoidf(fp[q]);
                const float a = 1.0f - fp[q];
                PA[q] *= a;
                PB[q] = fmaf(a, PB[q], fp[q] * zp[q]);
            }
        }

        // child 2 (O-child) scanB
        {
            float z[4], f[4], o[4];
            ldh4(V2 + vi, z);
            ldh4(V2 + vi + HID, f);
            ldh4(V2 + vi + 2 * HID, o);
            if (CI) {
                const float2 t = *(const float2*)(T2 + (size_t)m * 2);
                float hf[4], ho[4];
                ldh4(G2F + (size_t)m * HID + h0, hf);
                ldh4(G2O + (size_t)m * HID + h0, ho);
                #pragma unroll
                for (int q = 0; q < 4; q++) {
                    f[q] = hf[q] * t.x + (1.0f - t.x) * f[q];
                    o[q] = ho[q] * t.y + (1.0f - t.y) * o[q];
                }
            }
            float h2[4];
            #pragma unroll
            for (int q = 0; q < 4; q++) {
                z[q] = fmaxf(z[q], 0.0f);
                f[q] = sigmoidf(f[q]);
                p2[q] = fmaf(f[q], z[q], (1.0f - f[q]) * p2[q]);
                h2[q] = p2[q] * sigmoidf(o[q]) + xv[q];
            }
            sth4(Ho2 + (size_t)m * HID + h0, h2);
        }
    }
    const size_t idx = ((size_t)p * NCHUNK + chunk) * LANES + L;
    *(float4*)&g_A[idx]  = make_float4(PA[0], PA[1], PA[2], PA[3]);
    *(float4*)&g_Bc[idx] = make_float4(PB[0], PB[1], PB[2], PB[3]);
}

// ---------------------------------------------------------------------------
// Root scanB (node 0), 4 h per thread
// ---------------------------------------------------------------------------
__global__ __launch_bounds__(128) void kroot_kernel(const float* __restrict__ X,
                                                    float* __restrict__ out) {
    const int chunk = blockIdx.y;
    const int l4 = blockIdx.x * 128 + threadIdx.x;
    const int b  = l4 >> 7;
    const int h0 = (l4 & 127) * 4;
    const int L = b * 512 + h0;
    const __half* Vn = g_V;
    const float* Tn = g_T;
    const __half* HF = g_Hh;
    const __half* HO = g_Hh + (size_t)1 * MROWS * HID;

    float c[4];
    #pragma unroll
    for (int q = 0; q < 4; q++) c[q] = 0.0f;
    {
        const float* Ap = g_A  + L;
        const float* Bp = g_Bc + L;
        #pragma unroll 2
        for (int j = 0; j < chunk; j++) {
            const float4 a  = *(const float4*)(Ap + (size_t)j * LANES);
            const float4 bb = *(const float4*)(Bp + (size_t)j * LANES);
            c[0] = fmaf(a.x, c[0], bb.x);
            c[1] = fmaf(a.y, c[1], bb.y);
            c[2] = fmaf(a.z, c[2], bb.z);
            c[3] = fmaf(a.w, c[3], bb.w);
        }
    }

    float cm[4];
    #pragma unroll
    for (int q = 0; q < 4; q++) cm[q] = -3.4e38f;

    const int s0 = chunk * CHLEN;
    #pragma unroll 4
    for (int si = 0; si < CHLEN; si++) {
        const int m = (s0 + si) * BATCH + b;
        const size_t vi = (size_t)m * N3 + h0;
        float z[4], f[4], o[4], hf[4], ho[4];
        ldh4(Vn + vi, z);
        ldh4(Vn + vi + HID, f);
        ldh4(Vn + vi + 2 * HID, o);
        const float2 t = *(const float2*)(Tn + (size_t)m * 2);
        ldh4(HF + (size_t)m * HID + h0, hf);
        ldh4(HO + (size_t)m * HID + h0, ho);
        const float4 xr = *(const float4*)(X + (size_t)m * DIM + h0);
        const float xv[4] = { xr.x, xr.y, xr.z, xr.w };
        float ov[4];
        #pragma unroll
        for (int q = 0; q < 4; q++) {
            f[q] = hf[q] * t.x + (1.0f - t.x) * f[q];
            o[q] = ho[q] * t.y + (1.0f - t.y) * o[q];
            z[q] = fmaxf(z[q], 0.0f);
            f[q] = sigmoidf(f[q]);
            c[q] = fmaf(f[q], z[q], (1.0f - f[q]) * c[q]);
            const float v = c[q] * sigmoidf(o[q]);
            cm[q] = fmaxf(cm[q], v);
            ov[q] = v + xv[q];
        }
        *(float4*)&out[(size_t)m * HID + h0] = make_float4(ov[0], ov[1], ov[2], ov[3]);
    }
    *(float4*)&g_CM[(size_t)chunk * LANES + L] = make_float4(cm[0], cm[1], cm[2], cm[3]);
}

__global__ __launch_bounds__(128) void cmax_kernel(float* __restrict__ cmax_out) {
    const int lane = blockIdx.x * 128 + threadIdx.x;
    float cm = -3.4e38f;
    #pragma unroll 4
    for (int j = 0; j < NCHUNK; j++)
        cm = fmaxf(cm, g_CM[(size_t)j * LANES + lane]);
    cmax_out[lane] = cm;
}

// ---------------------------------------------------------------------------
extern "C" void kernel_launch(void* const* d_in, const int* in_sizes, int n_in,
                              void* d_out, int out_size) {
    const float* X  = (const float*)d_in[0];
    const float* Wp = (const float*)d_in[1];
    const float* WT = (const float*)d_in[2];
    const float* bT = (const float*)d_in[3];
    float* out = (float*)d_out;
    (void)in_sizes; (void)n_in;

    cudaFuncSetAttribute(k1_kernel,
                         cudaFuncAttributeMaxDynamicSharedMemorySize, GEMM_SMEM);
    cudaFuncSetAttribute(k2_kernel,
                         cudaFuncAttributeMaxDynamicSharedMemorySize, GEMM_SMEM);

    // 1: fp16 conversions
    conv_kernel<<<XH_BLOCKS + WH_BLOCKS, 256>>>(X, Wp);
    // 2: leaf GEMMs + tproj
    k1_kernel<<<4 * GPN + TP_GRID, 256, GEMM_SMEM>>>(X, WT, bT);
    // 3: internal GEMMs + scanA leaves
    k2_kernel<<<3 * GPN + SCANA_GRID, 256, GEMM_SMEM>>>();
    // 4: scanB(3,4)->scanA(1), scanB(5,6)->scanA(2)   <-- ncu slot
    klevel_kernel<false><<<dim3(LANES4 / 128, NCHUNK, 2), 128>>>(1, X);
    // 5: scanB(1,2)->scanA(0)
    klevel_kernel<true><<<dim3(LANES4 / 128, NCHUNK, 1), 128>>>(0, X);
    // 6: root scanB + per-chunk cmax
    kroot_kernel<<<dim3(LANES4 / 128, NCHUNK), 128>>>(X, out);
    // 7: cmax second output
    if (out_size >= MROWS * HID + LANES)
        cmax_kernel<<<LANES / 128, 128>>>(out + (size_t)MROWS * HID);
}

// round 17
// speedup vs baseline: 1.0706x; 1.0454x over previous
#include <cuda_runtime.h>
#include <cuda_fp16.h>
#include <math.h>
#include <stdint.h>

// Problem constants
#define S_LEN   2048
#define BATCH   8
#define DIM     512
#define HID     512
#define N3      1536
#define MROWS   16384
#define NODES   7
#define NCHUNK  64
#define CHLEN   32                    // S_LEN / NCHUNK
#define LANES   4096
#define LANES4  1024                  // leaf scanA: 4 h per thread
#define LANES2  2048                  // klevel/kroot: 2 h per thread

// fp16 GEMM tiling: 128x128 block tile, BK=64, 8 warps of 64x32, mma m16n8k16
#define BM 128
#define BN 128
#define BK 64
#define NKT (DIM / BK)                // 8 k-tiles
#define APITCH 72
#define BPITCH 136
#define A_ST (BM * APITCH * 2)        // 18432 B
#define B_ST (BK * BPITCH * 2)        // 17408 B
#define STAGE_B (A_ST + B_ST)         // 35840
#define GEMM_SMEM (3 * STAGE_B)       // 107520

#define GPN 1536                      // GEMM blocks per node: 12 * 128
#define TP_GRID 64
#define SCANA_GRID 1024               // 4 nodes * 64 chunks * 4 xb (256 thr)

// conversion grid
#define XH_BLOCKS 4096
#define WH_BLOCKS 2688

// Scratch (static __device__ arrays: allocation-free, graph-safe)
__device__ __align__(256) __half g_V [(size_t)NODES * MROWS * N3];
__device__ __align__(256) __half g_Hh[(size_t)6 * MROWS * HID];
__device__ __align__(256) float  g_T [(size_t)NODES * MROWS * 2];
__device__ __align__(256) float  g_A [(size_t)NODES * NCHUNK * LANES];
__device__ __align__(256) float  g_Bc[(size_t)NODES * NCHUNK * LANES];
__device__ __align__(256) float  g_CM[(size_t)NCHUNK * LANES];
__device__ __align__(256) __half g_Xh[(size_t)MROWS * DIM];
__device__ __align__(256) __half g_Wh[(size_t)NODES * DIM * N3];

__device__ __forceinline__ float sigmoidf(float x) {
    return __fdividef(1.0f, 1.0f + __expf(-x));
}
__device__ __forceinline__ uint32_t smem_u32(const void* p) {
    return (uint32_t)__cvta_generic_to_shared(p);
}
__device__ __forceinline__ void cp_async16(uint32_t dst, const void* src) {
    asm volatile("cp.async.cg.shared.global [%0], [%1], 16;\n" :: "r"(dst), "l"(src));
}
__device__ __forceinline__ void cp_commit() { asm volatile("cp.async.commit_group;\n"); }
template<int N> __device__ __forceinline__ void cp_wait() {
    asm volatile("cp.async.wait_group %0;\n" :: "n"(N));
}
__device__ __forceinline__ void ldsm_x4(uint32_t* r, uint32_t addr) {
    asm volatile("ldmatrix.sync.aligned.m8n8.x4.shared.b16 {%0,%1,%2,%3}, [%4];"
                 : "=r"(r[0]), "=r"(r[1]), "=r"(r[2]), "=r"(r[3]) : "r"(addr));
}
__device__ __forceinline__ void ldsm_x4_t(uint32_t* r, uint32_t addr) {
    asm volatile("ldmatrix.sync.aligned.m8n8.x4.trans.shared.b16 {%0,%1,%2,%3}, [%4];"
                 : "=r"(r[0]), "=r"(r[1]), "=r"(r[2]), "=r"(r[3]) : "r"(addr));
}
__device__ __forceinline__ void mma_f16(float* c, const uint32_t* a,
                                        uint32_t b0, uint32_t b1) {
    asm volatile(
        "mma.sync.aligned.m16n8k16.row.col.f32.f16.f16.f32 "
        "{%0,%1,%2,%3}, {%4,%5,%6,%7}, {%8,%9}, {%0,%1,%2,%3};\n"
        : "+f"(c[0]), "+f"(c[1]), "+f"(c[2]), "+f"(c[3])
        : "r"(a[0]), "r"(a[1]), "r"(a[2]), "r"(a[3]), "r"(b0), "r"(b1));
}

// vector load/store helpers for the scans
__device__ __forceinline__ void ldh4(const __half* p, float* o) {
    uint2 u = *(const uint2*)p;
    __half2 h0 = *reinterpret_cast<__half2*>(&u.x);
    __half2 h1 = *reinterpret_cast<__half2*>(&u.y);
    float2 a = __half22float2(h0), b = __half22float2(h1);
    o[0] = a.x; o[1] = a.y; o[2] = b.x; o[3] = b.y;
}
__device__ __forceinline__ void ldh2(const __half* p, float* o) {
    float2 v = __half22float2(*(const __half2*)p);
    o[0] = v.x; o[1] = v.y;
}
__device__ __forceinline__ void sth2(__half* p, const float* o) {
    *(__half2*)p = __floats2half2_rn(o[0], o[1]);
}

// ---------------------------------------------------------------------------
// conv: X->fp16 | W->fp16
// ---------------------------------------------------------------------------
__global__ __launch_bounds__(256) void conv_kernel(const float* __restrict__ X,
                                                   const float* __restrict__ Wp) {
    const int bid = blockIdx.x;
    const int tid = threadIdx.x;
    const float* src;
    __half* dst;
    size_t e0;
    if (bid < XH_BLOCKS) {
        e0 = (size_t)bid * 2048 + tid * 8;
        src = X; dst = g_Xh;
    } else {
        e0 = (size_t)(bid - XH_BLOCKS) * 2048 + tid * 8;
        src = Wp; dst = g_Wh;
    }
    const float4 v0 = *(const float4*)(src + e0);
    const float4 v1 = *(const float4*)(src + e0 + 4);
    __half2 h[4];
    h[0] = __floats2half2_rn(v0.x, v0.y);
    h[1] = __floats2half2_rn(v0.z, v0.w);
    h[2] = __floats2half2_rn(v1.x, v1.y);
    h[3] = __floats2half2_rn(v1.z, v1.w);
    *(uint4*)(dst + e0) = *(uint4*)h;
}

// ---------------------------------------------------------------------------
// GEMM body (R13 config, confirmed local optimum)
// ---------------------------------------------------------------------------
__device__ __forceinline__ void gemm_stage_load(uint32_t aB, uint32_t bB,
                                                const __half* __restrict__ Ag,
                                                const __half* __restrict__ Bg,
                                                int k0, int tid) {
    #pragma unroll
    for (int i = 0; i < 4; i++) {
        const int id = i * 256 + tid;
        const int m = id >> 3, c = id & 7;
        cp_async16(aB + (uint32_t)(m * (APITCH * 2) + c * 16),
                   Ag + (size_t)m * DIM + k0 + c * 8);
    }
    #pragma unroll
    for (int i = 0; i < 4; i++) {
        const int id = i * 256 + tid;
        const int k = id >> 4, c = id & 15;
        cp_async16(bB + (uint32_t)(k * (BPITCH * 2) + c * 16),
                   Bg + (size_t)(k0 + k) * N3 + c * 8);
    }
    cp_commit();
}

__device__ void gemm_body(char* dynsmem, int node, int mb, int nb, int tid) {
    const int n0 = nb * BN;
    const int m0 = mb * BM;
    const __half* Ag = g_Xh + (size_t)m0 * DIM;
    const __half* Bg = g_Wh + (size_t)node * DIM * N3 + n0;
    __half* C = g_V + (size_t)node * MROWS * N3;

    const int w = tid >> 5;
    const int lane = tid & 31;
    const int gid = lane >> 2;
    const int tig = lane & 3;
    const int wm = (w >> 2) * 64;
    const int wn = (w & 3) * 32;

    const int rowb = (lane & 7) + ((lane >> 3) & 1) * 8;
    const int choff = lane >> 4;

    const uint32_t sbase = smem_u32(dynsmem);

    float acc[4][4][4];
    #pragma unroll
    for (int mi = 0; mi < 4; mi++)
        #pragma unroll
        for (int ni = 0; ni < 4; ni++)
            #pragma unroll
            for (int c = 0; c < 4; c++) acc[mi][ni][c] = 0.0f;

    gemm_stage_load(sbase, sbase + A_ST, Ag, Bg, 0, tid);
    gemm_stage_load(sbase + STAGE_B, sbase + STAGE_B + A_ST, Ag, Bg, BK, tid);

    int s = 0;
    #pragma unroll 1
    for (int kt = 0; kt < NKT; kt++) {
        if (kt == NKT - 1) cp_wait<0>(); else cp_wait<1>();
        __syncthreads();
        if (kt + 2 < NKT) {
            const int ps = (s + 2 >= 3) ? (s - 1) : (s + 2);
            gemm_stage_load(sbase + (uint32_t)ps * STAGE_B,
                            sbase + (uint32_t)ps * STAGE_B + A_ST,
                            Ag, Bg, (kt + 2) * BK, tid);
        }

        const uint32_t aBase = sbase + (uint32_t)s * STAGE_B;
        const uint32_t bBase = aBase + A_ST;

        #pragma unroll
        for (int j = 0; j < 4; j++) {
            uint32_t a[4][4], b[2][4];
            #pragma unroll
            for (int mi = 0; mi < 4; mi++) {
                const int row = wm + mi * 16 + rowb;
                const int chunk = 2 * j + choff;
                ldsm_x4(a[mi], aBase + (uint32_t)(row * (APITCH * 2) + chunk * 16));
            }
            #pragma unroll
            for (int p = 0; p < 2; p++) {
                const int row = 16 * j + rowb;
                const int chunk = (wn >> 3) + 2 * p + choff;
                ldsm_x4_t(b[p], bBase + (uint32_t)(row * (BPITCH * 2) + chunk * 16));
            }
            #pragma unroll
            for (int mi = 0; mi < 4; mi++)
                #pragma unroll
                for (int ni = 0; ni < 4; ni++)
                    mma_f16(acc[mi][ni], a[mi],
                            b[ni >> 1][(ni & 1) * 2], b[ni >> 1][(ni & 1) * 2 + 1]);
        }
        s = (s + 1 >= 3) ? 0 : (s + 1);
    }

    #pragma unroll
    for (int mi = 0; mi < 4; mi++) {
        #pragma unroll
        for (int ni = 0; ni < 4; ni++) {
            const int row = m0 + wm + mi * 16 + gid;
            const int col = n0 + wn + ni * 8 + tig * 2;
            *(__half2*)&C[(size_t)row * N3 + col] =
                __floats2half2_rn(acc[mi][ni][0], acc[mi][ni][1]);
            *(__half2*)&C[(size_t)(row + 8) * N3 + col] =
                __floats2half2_rn(acc[mi][ni][2], acc[mi][ni][3]);
        }
    }
}

// ---------------------------------------------------------------------------
// tproj body: all 7 nodes' gates, W_T table in dynamic smem
// ---------------------------------------------------------------------------
__device__ void tproj_body(char* dynsmem, int blk,
                           const float* __restrict__ X,
                           const float* __restrict__ WT,
                           const float* __restrict__ bT, int tid) {
    float (*swt)[NODES][DIM] = (float (*)[NODES][DIM])dynsmem;
    for (int idx = tid; idx < NODES * DIM * 2; idx += 256) {
        const int node = idx / (DIM * 2);
        const int r = idx - node * DIM * 2;
        swt[r & 1][node][r >> 1] = WT[idx];
    }
    __syncthreads();

    const int w = tid >> 5;
    const int lane = tid & 31;
    const int m0 = blk * 256 + w * 32;

    float bt[NODES][2];
    #pragma unroll
    for (int n = 0; n < NODES; n++) {
        bt[n][0] = bT[n * 2 + 0];
        bt[n][1] = bT[n * 2 + 1];
    }
    for (int r = 0; r < 32; r++) {
        const int m = m0 + r;
        const float* xr = X + (size_t)m * DIM;
        float s[NODES][2];
        #pragma unroll
        for (int n = 0; n < NODES; n++) s[n][0] = s[n][1] = 0.0f;
        #pragma unroll 4
        for (int k = lane; k < DIM; k += 32) {
            const float x = xr[k];
            #pragma unroll
            for (int n = 0; n < NODES; n++) {
                s[n][0] = fmaf(x, swt[0][n][k], s[n][0]);
                s[n][1] = fmaf(x, swt[1][n][k], s[n][1]);
            }
        }
        #pragma unroll
        for (int n = 0; n < NODES; n++)
            #pragma unroll
            for (int j = 0; j < 2; j++)
                #pragma unroll
                for (int o = 16; o > 0; o >>= 1)
                    s[n][j] += __shfl_down_sync(0xFFFFFFFFu, s[n][j], o);
        if (lane == 0) {
            #pragma unroll
            for (int n = 0; n < NODES; n++) {
                const size_t t = ((size_t)n * MROWS + m) * 2;
                g_T[t + 0] = sigmoidf(s[n][0] + bt[n][0]);
                g_T[t + 1] = sigmoidf(s[n][1] + bt[n][1]);
            }
        }
    }
}

// ---------------------------------------------------------------------------
// scanA leaf body (4 h per thread; rides in k2's GEMM shadow)
// ---------------------------------------------------------------------------
__device__ void scanA_body(int node, int chunk, int l4) {
    const int b  = l4 >> 7;
    const int h0 = (l4 & 127) * 4;
    const __half* Vn = g_V + (size_t)node * MROWS * N3;

    float A[4], Bs[4];
    #pragma unroll
    for (int q = 0; q < 4; q++) { A[q] = 1.0f; Bs[q] = 0.0f; }

    const int s0 = chunk * CHLEN;
    #pragma unroll 4
    for (int si = 0; si < CHLEN; si++) {
        const int m = (s0 + si) * BATCH + b;
        const size_t vi = (size_t)m * N3 + h0;
        float z[4], f[4];
        ldh4(Vn + vi, z);
        ldh4(Vn + vi + HID, f);
        #pragma unroll
        for (int q = 0; q < 4; q++) {
            z[q] = fmaxf(z[q], 0.0f);
            f[q] = sigmoidf(f[q]);
            const float a = 1.0f - f[q];
            A[q] *= a;
            Bs[q] = fmaf(a, Bs[q], f[q] * z[q]);
        }
    }
    const size_t idx = ((size_t)node * NCHUNK + chunk) * LANES + b * 512 + h0;
    *(float4*)&g_A[idx]  = make_float4(A[0], A[1], A[2], A[3]);
    *(float4*)&g_Bc[idx] = make_float4(Bs[0], Bs[1], Bs[2], Bs[3]);
}

// ---------------------------------------------------------------------------
// K1: leaf GEMMs (nodes 3..6) + tproj
// ---------------------------------------------------------------------------
__global__ __launch_bounds__(256, 2) void k1_kernel(const float* __restrict__ X,
                                                    const float* __restrict__ WT,
                                                    const float* __restrict__ bT) {
    extern __shared__ __align__(16) char dynsmem[];
    const int bid = blockIdx.x;
    const int tid = threadIdx.x;
    if (bid < 4 * GPN) {
        const int node = 3 + bid / GPN;
        const int r = bid % GPN;
        gemm_body(dynsmem, node, r / 12, r % 12, tid);
    } else {
        tproj_body(dynsmem, bid - 4 * GPN, X, WT, bT, tid);
    }
}

// ---------------------------------------------------------------------------
// K2: internal GEMMs (nodes 0..2) + scanA for leaves
// ---------------------------------------------------------------------------
__global__ __launch_bounds__(256, 2) void k2_kernel() {
    extern __shared__ __align__(16) char dynsmem[];
    const int bid = blockIdx.x;
    const int tid = threadIdx.x;
    if (bid < 3 * GPN) {
        const int node = bid / GPN;
        const int r = bid % GPN;
        gemm_body(dynsmem, node, r / 12, r % 12, tid);
    } else {
        const int sid = bid - 3 * GPN;            // 0..1023
        const int node = 3 + (sid >> 8);
        const int rem = sid & 255;
        const int chunk = rem >> 2;
        const int xb = rem & 3;
        scanA_body(node, chunk, xb * 256 + tid);
    }
}

// ---------------------------------------------------------------------------
// Level kernel: scanB(children) fused with scanA(parent), 2 h per thread.
// Grid (16, 64, n) = 2x the blocks of the 4h version; same total work.
// ---------------------------------------------------------------------------
template<bool CI>
__global__ __launch_bounds__(128) void klevel_kernel(int p0, const float* __restrict__ X) {
    const int p  = p0 + blockIdx.z;
    const int c1 = 2 * p + 1;
    const int c2 = 2 * p + 2;
    const int chunk = blockIdx.y;
    const int l2 = blockIdx.x * 128 + threadIdx.x;   // 0..2047
    const int b  = l2 >> 8;
    const int h0 = (l2 & 255) * 2;
    const int L = b * 512 + h0;

    const __half* V1 = g_V + (size_t)c1 * MROWS * N3;
    const __half* V2 = g_V + (size_t)c2 * MROWS * N3;
    const __half* Vp = g_V + (size_t)p  * MROWS * N3;
    const float* T1 = g_T + (size_t)c1 * MROWS * 2;
    const float* T2 = g_T + (size_t)c2 * MROWS * 2;
    const float* Tp = g_T + (size_t)p  * MROWS * 2;
    const __half* G1F = g_Hh + (size_t)(2 * c1) * MROWS * HID;
    const __half* G1O = g_Hh + (size_t)(2 * c1 + 1) * MROWS * HID;
    const __half* G2F = g_Hh + (size_t)(2 * c2) * MROWS * HID;
    const __half* G2O = g_Hh + (size_t)(2 * c2 + 1) * MROWS * HID;
    __half* Ho1 = g_Hh + (size_t)(c1 - 1) * MROWS * HID;
    __half* Ho2 = g_Hh + (size_t)(c2 - 1) * MROWS * HID;

    float p1[2], p2[2];
    #pragma unroll
    for (int q = 0; q < 2; q++) { p1[q] = 0.0f; p2[q] = 0.0f; }
    {
        const float* A1p = g_A  + (size_t)c1 * NCHUNK * LANES + L;
        const float* B1p = g_Bc + (size_t)c1 * NCHUNK * LANES + L;
        const float* A2p = g_A  + (size_t)c2 * NCHUNK * LANES + L;
        const float* B2p = g_Bc + (size_t)c2 * NCHUNK * LANES + L;
        #pragma unroll 4
        for (int j = 0; j < chunk; j++) {
            const float2 a1 = *(const float2*)(A1p + (size_t)j * LANES);
            const float2 b1 = *(const float2*)(B1p + (size_t)j * LANES);
            const float2 a2 = *(const float2*)(A2p + (size_t)j * LANES);
            const float2 b2 = *(const float2*)(B2p + (size_t)j * LANES);
            p1[0] = fmaf(a1.x, p1[0], b1.x);
            p1[1] = fmaf(a1.y, p1[1], b1.y);
            p2[0] = fmaf(a2.x, p2[0], b2.x);
            p2[1] = fmaf(a2.y, p2[1], b2.y);
        }
    }

    float PA[2], PB[2];
    #pragma unroll
    for (int q = 0; q < 2; q++) { PA[q] = 1.0f; PB[q] = 0.0f; }

    const int s0 = chunk * CHLEN;
    #pragma unroll 4
    for (int si = 0; si < CHLEN; si++) {
        const int m = (s0 + si) * BATCH + b;
        const float2 xr = *(const float2*)(X + (size_t)m * DIM + h0);
        const float xv[2] = { xr.x, xr.y };
        const size_t vi = (size_t)m * N3 + h0;

        // child 1 (F-child) scanB + parent scanA
        {
            float z[2], f[2], o[2];
            ldh2(V1 + vi, z);
            ldh2(V1 + vi + HID, f);
            ldh2(V1 + vi + 2 * HID, o);
            if (CI) {
                const float2 t = *(const float2*)(T1 + (size_t)m * 2);
                float hf[2], ho[2];
                ldh2(G1F + (size_t)m * HID + h0, hf);
                ldh2(G1O + (size_t)m * HID + h0, ho);
                #pragma unroll
                for (int q = 0; q < 2; q++) {
                    f[q] = hf[q] * t.x + (1.0f - t.x) * f[q];
                    o[q] = ho[q] * t.y + (1.0f - t.y) * o[q];
                }
            }
            float h1[2];
            #pragma unroll
            for (int q = 0; q < 2; q++) {
                z[q] = fmaxf(z[q], 0.0f);
                f[q] = sigmoidf(f[q]);
                p1[q] = fmaf(f[q], z[q], (1.0f - f[q]) * p1[q]);
                h1[q] = p1[q] * sigmoidf(o[q]) + xv[q];
            }
            sth2(Ho1 + (size_t)m * HID + h0, h1);

            const float tp = __ldg(Tp + (size_t)m * 2);
            float zp[2], fp[2];
            ldh2(Vp + vi, zp);
            ldh2(Vp + vi + HID, fp);
            #pragma unroll
            for (int q = 0; q < 2; q++) {
                fp[q] = h1[q] * tp + (1.0f - tp) * fp[q];
                zp[q] = fmaxf(zp[q], 0.0f);
                fp[q] = sigmoidf(fp[q]);
                const float a = 1.0f - fp[q];
                PA[q] *= a;
                PB[q] = fmaf(a, PB[q], fp[q] * zp[q]);
            }
        }

        // child 2 (O-child) scanB
        {
            float z[2], f[2], o[2];
            ldh2(V2 + vi, z);
            ldh2(V2 + vi + HID, f);
            ldh2(V2 + vi + 2 * HID, o);
            if (CI) {
                const float2 t = *(const float2*)(T2 + (size_t)m * 2);
                float hf[2], ho[2];
                ldh2(G2F + (size_t)m * HID + h0, hf);
                ldh2(G2O + (size_t)m * HID + h0, ho);
                #pragma unroll
                for (int q = 0; q < 2; q++) {
                    f[q] = hf[q] * t.x + (1.0f - t.x) * f[q];
                    o[q] = ho[q] * t.y + (1.0f - t.y) * o[q];
                }
            }
            float h2[2];
            #pragma unroll
            for (int q = 0; q < 2; q++) {
                z[q] = fmaxf(z[q], 0.0f);
                f[q] = sigmoidf(f[q]);
                p2[q] = fmaf(f[q], z[q], (1.0f - f[q]) * p2[q]);
                h2[q] = p2[q] * sigmoidf(o[q]) + xv[q];
            }
            sth2(Ho2 + (size_t)m * HID + h0, h2);
        }
    }
    const size_t idx = ((size_t)p * NCHUNK + chunk) * LANES + L;
    *(float2*)&g_A[idx]  = make_float2(PA[0], PA[1]);
    *(float2*)&g_Bc[idx] = make_float2(PB[0], PB[1]);
}

// ---------------------------------------------------------------------------
// Root scanB (node 0), 2 h per thread
// ---------------------------------------------------------------------------
__global__ __launch_bounds__(128) void kroot_kernel(const float* __restrict__ X,
                                                    float* __restrict__ out) {
    const int chunk = blockIdx.y;
    const int l2 = blockIdx.x * 128 + threadIdx.x;
    const int b  = l2 >> 8;
    const int h0 = (l2 & 255) * 2;
    const int L = b * 512 + h0;
    const __half* Vn = g_V;
    const float* Tn = g_T;
    const __half* HF = g_Hh;
    const __half* HO = g_Hh + (size_t)1 * MROWS * HID;

    float c[2] = {0.0f, 0.0f};
    {
        const float* Ap = g_A  + L;
        const float* Bp = g_Bc + L;
        #pragma unroll 4
        for (int j = 0; j < chunk; j++) {
            const float2 a  = *(const float2*)(Ap + (size_t)j * LANES);
            const float2 bb = *(const float2*)(Bp + (size_t)j * LANES);
            c[0] = fmaf(a.x, c[0], bb.x);
            c[1] = fmaf(a.y, c[1], bb.y);
        }
    }

    float cm[2] = {-3.4e38f, -3.4e38f};
    const int s0 = chunk * CHLEN;
    #pragma unroll 4
    for (int si = 0; si < CHLEN; si++) {
        const int m = (s0 + si) * BATCH + b;
        const size_t vi = (size_t)m * N3 + h0;
        float z[2], f[2], o[2], hf[2], ho[2];
        ldh2(Vn + vi, z);
        ldh2(Vn + vi + HID, f);
        ldh2(Vn + vi + 2 * HID, o);
        const float2 t = *(const float2*)(Tn + (size_t)m * 2);
        ldh2(HF + (size_t)m * HID + h0, hf);
        ldh2(HO + (size_t)m * HID + h0, ho);
        const float2 xr = *(const float2*)(X + (size_t)m * DIM + h0);
        const float xv[2] = { xr.x, xr.y };
        float ov[2];
        #pragma unroll
        for (int q = 0; q < 2; q++) {
            f[q] = hf[q] * t.x + (1.0f - t.x) * f[q];
            o[q] = ho[q] * t.y + (1.0f - t.y) * o[q];
            z[q] = fmaxf(z[q], 0.0f);
            f[q] = sigmoidf(f[q]);
            c[q] = fmaf(f[q], z[q], (1.0f - f[q]) * c[q]);
            const float v = c[q] * sigmoidf(o[q]);
            cm[q] = fmaxf(cm[q], v);
            ov[q] = v + xv[q];
        }
        *(float2*)&out[(size_t)m * HID + h0] = make_float2(ov[0], ov[1]);
    }
    *(float2*)&g_CM[(size_t)chunk * LANES + L] = make_float2(cm[0], cm[1]);
}

__global__ __launch_bounds__(128) void cmax_kernel(float* __restrict__ cmax_out) {
    const int lane = blockIdx.x * 128 + threadIdx.x;
    float cm = -3.4e38f;
    #pragma unroll 4
    for (int j = 0; j < NCHUNK; j++)
        cm = fmaxf(cm, g_CM[(size_t)j * LANES + lane]);
    cmax_out[lane] = cm;
}

// ---------------------------------------------------------------------------
extern "C" void kernel_launch(void* const* d_in, const int* in_sizes, int n_in,
                              void* d_out, int out_size) {
    const float* X  = (const float*)d_in[0];
    const float* Wp = (const float*)d_in[1];
    const float* WT = (const float*)d_in[2];
    const float* bT = (const float*)d_in[3];
    float* out = (float*)d_out;
    (void)in_sizes; (void)n_in;

    cudaFuncSetAttribute(k1_kernel,
                         cudaFuncAttributeMaxDynamicSharedMemorySize, GEMM_SMEM);
    cudaFuncSetAttribute(k2_kernel,
                         cudaFuncAttributeMaxDynamicSharedMemorySize, GEMM_SMEM);

    // 1: fp16 conversions
    conv_kernel<<<XH_BLOCKS + WH_BLOCKS, 256>>>(X, Wp);
    // 2: leaf GEMMs + tproj (block-range fusion)
    k1_kernel<<<4 * GPN + TP_GRID, 256, GEMM_SMEM>>>(X, WT, bT);
    // 3: internal GEMMs + scanA leaves
    k2_kernel<<<3 * GPN + SCANA_GRID, 256, GEMM_SMEM>>>();
    // 4: scanB(3,4)->scanA(1), scanB(5,6)->scanA(2)   <-- ncu slot
    klevel_kernel<false><<<dim3(LANES2 / 128, NCHUNK, 2), 128>>>(1, X);
    // 5: scanB(1,2)->scanA(0)
    klevel_kernel<true><<<dim3(LANES2 / 128, NCHUNK, 1), 128>>>(0, X);
    // 6: root scanB + per-chunk cmax
    kroot_kernel<<<dim3(LANES2 / 128, NCHUNK), 128>>>(X, out);
    // 7: cmax second output
    if (out_size >= MROWS * HID + LANES)
        cmax_kernel<<<LANES / 128, 128>>>(out + (size_t)MROWS * HID);
}